// round 5
// baseline (speedup 1.0000x reference)
#include <cuda_runtime.h>
#include <cuda_bf16.h>
#include <math.h>

// PolarVoxelizer R5: PDL-overlapped 3-kernel graph + fast-path K1.
//   memset(g_cnt) -> K1 k_indices (compacting) -> [PDL] K2 k_zero -> K3 k_scatter
// K1 pre-rejects by geometry (x<=0, |y|>2.2x) so only ~36% of points run
// atan2f; int-div replaced by exact magic multiply; valid lins compacted
// warp-aggregated into g_lin.

#define Z_DEPTH   100
#define HALF_FOV  1.134f
#define R_MIN_C   2.7f
#define R_MAX_C   165.0f
#define SLOPE_REJ 2.2f        // atan(2.2)=1.1441 > HALF_FOV + any fp slop
#define MAX_RB    512
#define MAX_AB    256
#define MAX_PTS   (1 << 20)

__device__ int g_lin[MAX_PTS];          // compacted linear indices
__device__ unsigned int g_cnt;           // count (memset to 0 each launch)

// Exact searchsorted(side='left') given an approximate starting index.
__device__ __forceinline__ int lb_fixup(const float* __restrict__ a, int n, float v, int idx) {
    idx = min(max(idx, 0), n);
    while (idx > 0 && a[idx - 1] >= v) --idx;
    while (idx < n && a[idx] < v) ++idx;
    return idx;
}

__global__ __launch_bounds__(256) void k_indices(
    const float4* __restrict__ lidars4,
    const float* __restrict__ r_bins,
    const float* __restrict__ angle_bins,
    int npts, int num_r, int num_a,
    unsigned long long div_magic,          // exact i/n_per_s via (i*magic)>>40
    float a0, float inv_astep,
    float log2_rmin, float inv_log2_1pd)
{
#if __CUDA_ARCH__ >= 900
    cudaTriggerProgrammaticLaunchCompletion();   // let K2 co-schedule now
#endif
    __shared__ float s_r[MAX_RB];
    __shared__ float s_a[MAX_AB];
    for (int i = threadIdx.x; i < num_r; i += blockDim.x) s_r[i] = r_bins[i];
    for (int i = threadIdx.x; i < num_a; i += blockDim.x) s_a[i] = angle_bins[i];
    __syncthreads();

    const int lane = threadIdx.x & 31;
    int c = blockIdx.x * blockDim.x + threadIdx.x;   // chunk of 4 points
    int nchunks = (npts + 3) >> 2;
    if (c >= nchunks) return;

    int base = c * 4;
    int v4 = c * 3;
    float4 q0 = lidars4[v4 + 0];
    float4 q1 = lidars4[v4 + 1];
    float4 q2 = lidars4[v4 + 2];
    float px[4] = {q0.x, q0.w, q1.z, q2.y};
    float py[4] = {q0.y, q1.x, q1.w, q2.z};
    float pz[4] = {q0.z, q1.y, q2.x, q2.w};

    #pragma unroll
    for (int k = 0; k < 4; ++k) {
        int i = base + k;
        int lin = -1;
        float x = px[k], y = py[k], z = pz[k];

        if (i < npts && x > 0.0f && fabsf(y) <= SLOPE_REJ * x) {
            // radius: bit-exact vs XLA f32 (no FMA contraction, IEEE sqrt)
            float radius = __fsqrt_rn(__fadd_rn(__fmul_rn(x, x), __fmul_rn(y, y)));
            if ((radius < R_MAX_C) && (radius > R_MIN_C)) {
                // angle: atan2f fast path, double refine near decision boundaries
                float v = atan2f(y, x);
                float eps = fmaxf(fabsf(v) * 1.0e-6f, 1.0e-7f);

                int yg0 = (int)floorf((v - a0) * inv_astep);
                int yg = lb_fixup(s_a, num_a, v, yg0);

                bool near = (fabsf(fabsf(v) - HALF_FOV) <= eps);
                if (yg < num_a && fabsf(v - s_a[yg])     <= eps) near = true;
                if (yg > 0     && fabsf(v - s_a[yg - 1]) <= eps) near = true;
                if (near) {
                    v = (float)atan2((double)y, (double)x);
                    yg = lb_fixup(s_a, num_a, v, yg);
                }
                if (fabsf(v) < HALF_FOV) {
                    int xg0 = (int)floorf((__log2f(radius) - log2_rmin) * inv_log2_1pd);
                    int xg = lb_fixup(s_r, num_r, radius, xg0);
                    int zg = (int)floorf(__fdiv_rn(__fsub_rn(z, -2.0f), 0.2f));
                    int s = (int)(((unsigned long long)i * div_magic) >> 40);
                    lin = ((s * Z_DEPTH + zg) * num_a + yg) * num_r + xg;
                }
            }
        }

        // warp-aggregated compaction
        unsigned int m = __ballot_sync(0xffffffffu, lin >= 0);
        if (m) {
            int leader = __ffs(m) - 1;
            unsigned int wbase = 0;
            if (lane == leader) wbase = atomicAdd(&g_cnt, (unsigned)__popc(m));
            wbase = __shfl_sync(0xffffffffu, wbase, leader);
            if (lin >= 0)
                g_lin[wbase + __popc(m & ((1u << lane) - 1u))] = lin;
        }
    }
}

__global__ __launch_bounds__(256) void k_zero(float4* __restrict__ out4, int n4)
{
    int tid = blockIdx.x * blockDim.x + threadIdx.x;
    int stride = gridDim.x * blockDim.x;
    float4 z = make_float4(0.f, 0.f, 0.f, 0.f);
    for (int j = tid; j < n4; j += stride) out4[j] = z;
}

__global__ __launch_bounds__(256) void k_scatter(float* __restrict__ out)
{
    unsigned int cnt = g_cnt;
    unsigned int i = blockIdx.x * blockDim.x + threadIdx.x;
    if (i < cnt) out[g_lin[i]] = 1.0f;
}

extern "C" void kernel_launch(void* const* d_in, const int* in_sizes, int n_in,
                              void* d_out, int out_size) {
    const float* lidars     = (const float*)d_in[0];
    const float* r_bins     = (const float*)d_in[1];
    const float* angle_bins = (const float*)d_in[2];
    float* out = (float*)d_out;

    const int B = 2;  // output keeps only batch 0
    int num_r = in_sizes[1];
    int num_a = in_sizes[2];
    int npts  = in_sizes[0] / (3 * B);
    int S     = out_size / (Z_DEPTH * num_a * num_r);
    int n_per_s = npts / S;

    // Analytic grid params (guesses only; exactness via lb_fixup)
    double fov = 2.268;
    float a0 = (float)(-fov / 2.0);
    float inv_astep = (float)((num_a - 1) / fov);
    double delta = pow((165.0 + 0.0001) / 2.7, 1.0 / (double)(num_r - 1)) - 1.0;
    float log2_rmin = (float)(log(2.7) / log(2.0));
    float inv_log2_1pd = (float)(log(2.0) / log(1.0 + delta));

    // Exact floor(i / n_per_s) for i < 2^20: magic = ceil(2^40 / n_per_s)
    unsigned long long div_magic =
        ((1ULL << 40) + (unsigned long long)n_per_s - 1ULL) / (unsigned long long)n_per_s;

    // reset compaction counter (graph-legal memset node)
    void* cnt_addr = nullptr;
    cudaGetSymbolAddress(&cnt_addr, g_cnt);
    cudaMemsetAsync(cnt_addr, 0, sizeof(unsigned int), 0);

    // --- K1: index compute + compaction (triggers early for PDL) ---
    int nchunks = (npts + 3) / 4;
    int k1_blocks = (nchunks + 255) / 256;
    k_indices<<<k1_blocks, 256>>>(
        (const float4*)lidars, r_bins, angle_bins,
        npts, num_r, num_a, div_magic,
        a0, inv_astep, log2_rmin, inv_log2_1pd);

    // --- K2: zero output, PDL-overlapped with K1 (independent memory) ---
    {
        int n4 = out_size / 4;
        int k2_blocks = 148 * 8;
        cudaLaunchConfig_t cfg = {};
        cfg.gridDim = dim3(k2_blocks, 1, 1);
        cfg.blockDim = dim3(256, 1, 1);
        cfg.dynamicSmemBytes = 0;
        cfg.stream = 0;
        cudaLaunchAttribute attr[1];
        attr[0].id = cudaLaunchAttributeProgrammaticStreamSerialization;
        attr[0].val.programmaticStreamSerializationAllowed = 1;
        cfg.attrs = attr;
        cfg.numAttrs = 1;
        float4* out4 = (float4*)out;
        cudaLaunchKernelEx(&cfg, k_zero, out4, n4);
    }

    // --- K3: scatter (normal launch: waits for BOTH K1 and K2) ---
    int k3_blocks = (npts + 255) / 256;
    k_scatter<<<k3_blocks, 256>>>(out);
}

// round 6
// speedup vs baseline: 1.5483x; 1.5483x over previous
#include <cuda_runtime.h>
#include <cuda_bf16.h>
#include <math.h>

// PolarVoxelizer R6: R4 structure (no atomics) + geometric pre-rejection.
//   K1 k_indices : per-point bin index or -1 -> g_lin[i] (latency-bound)
//   K2 k_zero    : float4 stream-zero of output (HBM-bound), PDL-overlapped w/ K1
//   K3 k_scatter : out[g_lin[i]] = 1.0f, normal launch (waits K1 & K2)

#define Z_DEPTH   100
#define HALF_FOV  1.134f
#define R_MIN_C   2.7f
#define R_MAX_C   165.0f
#define SLOPE_REJ 2.2f        // atan(2.2)=1.1441 > HALF_FOV + any fp slop
#define MAX_RB    512
#define MAX_AB    256
#define MAX_PTS   (1 << 20)

__device__ int g_lin[MAX_PTS];   // per-point linear index or -1

// Exact searchsorted(side='left') given an approximate starting index.
__device__ __forceinline__ int lb_fixup(const float* __restrict__ a, int n, float v, int idx) {
    idx = min(max(idx, 0), n);
    while (idx > 0 && a[idx - 1] >= v) --idx;
    while (idx < n && a[idx] < v) ++idx;
    return idx;
}

__global__ __launch_bounds__(256) void k_indices(
    const float4* __restrict__ lidars4,
    const float* __restrict__ r_bins,
    const float* __restrict__ angle_bins,
    int npts, int num_r, int num_a,
    unsigned long long div_magic,          // exact i/n_per_s via (i*magic)>>40
    float a0, float inv_astep,
    float log2_rmin, float inv_log2_1pd)
{
#if __CUDA_ARCH__ >= 900
    cudaTriggerProgrammaticLaunchCompletion();   // let K2 co-schedule now
#endif
    __shared__ float s_r[MAX_RB];
    __shared__ float s_a[MAX_AB];
    for (int i = threadIdx.x; i < num_r; i += blockDim.x) s_r[i] = r_bins[i];
    for (int i = threadIdx.x; i < num_a; i += blockDim.x) s_a[i] = angle_bins[i];
    __syncthreads();

    int c = blockIdx.x * blockDim.x + threadIdx.x;   // chunk of 4 points
    int nchunks = (npts + 3) >> 2;
    if (c >= nchunks) return;

    int base = c * 4;
    int v4 = c * 3;
    float4 q0 = lidars4[v4 + 0];
    float4 q1 = lidars4[v4 + 1];
    float4 q2 = lidars4[v4 + 2];
    float px[4] = {q0.x, q0.w, q1.z, q2.y};
    float py[4] = {q0.y, q1.x, q1.w, q2.z};
    float pz[4] = {q0.z, q1.y, q2.x, q2.w};

    int lins[4];
    #pragma unroll
    for (int k = 0; k < 4; ++k) {
        int i = base + k;
        int lin = -1;
        float x = px[k], y = py[k], z = pz[k];

        // geometric pre-rejection: provably outside FOV (|angle| > 1.1441)
        if (i < npts && x > 0.0f && fabsf(y) <= SLOPE_REJ * x) {
            // radius: bit-exact vs XLA f32 (no FMA contraction, IEEE sqrt)
            float radius = __fsqrt_rn(__fadd_rn(__fmul_rn(x, x), __fmul_rn(y, y)));
            if ((radius < R_MAX_C) && (radius > R_MIN_C)) {
                // angle: atan2f fast path, double refine near decision boundaries
                float v = atan2f(y, x);
                float eps = fmaxf(fabsf(v) * 1.0e-6f, 1.0e-7f);

                int yg0 = (int)floorf((v - a0) * inv_astep);
                int yg = lb_fixup(s_a, num_a, v, yg0);

                bool near = (fabsf(fabsf(v) - HALF_FOV) <= eps);
                if (yg < num_a && fabsf(v - s_a[yg])     <= eps) near = true;
                if (yg > 0     && fabsf(v - s_a[yg - 1]) <= eps) near = true;
                if (near) {
                    v = (float)atan2((double)y, (double)x);
                    yg = lb_fixup(s_a, num_a, v, yg);
                }
                if (fabsf(v) < HALF_FOV) {
                    int xg0 = (int)floorf((__log2f(radius) - log2_rmin) * inv_log2_1pd);
                    int xg = lb_fixup(s_r, num_r, radius, xg0);
                    int zg = (int)floorf(__fdiv_rn(__fsub_rn(z, -2.0f), 0.2f));
                    int s = (int)(((unsigned long long)i * div_magic) >> 40);
                    lin = ((s * Z_DEPTH + zg) * num_a + yg) * num_r + xg;
                }
            }
        }
        lins[k] = lin;
    }

    // coalesced 16B store of 4 results (base = 4*c, always aligned)
    if (base + 3 < npts) {
        *(int4*)&g_lin[base] = make_int4(lins[0], lins[1], lins[2], lins[3]);
    } else {
        #pragma unroll
        for (int k = 0; k < 4; ++k)
            if (base + k < npts) g_lin[base + k] = lins[k];
    }
}

__global__ __launch_bounds__(256) void k_zero(float4* __restrict__ out4, int n4)
{
    int tid = blockIdx.x * blockDim.x + threadIdx.x;
    int stride = gridDim.x * blockDim.x;
    float4 z = make_float4(0.f, 0.f, 0.f, 0.f);
    for (int j = tid; j < n4; j += stride) out4[j] = z;
}

__global__ __launch_bounds__(256) void k_scatter(float* __restrict__ out, int npts)
{
    int i = blockIdx.x * blockDim.x + threadIdx.x;
    if (i >= npts) return;
    int lin = g_lin[i];
    if (lin >= 0) out[lin] = 1.0f;
}

extern "C" void kernel_launch(void* const* d_in, const int* in_sizes, int n_in,
                              void* d_out, int out_size) {
    const float* lidars     = (const float*)d_in[0];
    const float* r_bins     = (const float*)d_in[1];
    const float* angle_bins = (const float*)d_in[2];
    float* out = (float*)d_out;

    const int B = 2;  // output keeps only batch 0
    int num_r = in_sizes[1];
    int num_a = in_sizes[2];
    int npts  = in_sizes[0] / (3 * B);
    int S     = out_size / (Z_DEPTH * num_a * num_r);
    int n_per_s = npts / S;

    // Analytic grid params (guesses only; exactness via lb_fixup)
    double fov = 2.268;
    float a0 = (float)(-fov / 2.0);
    float inv_astep = (float)((num_a - 1) / fov);
    double delta = pow((165.0 + 0.0001) / 2.7, 1.0 / (double)(num_r - 1)) - 1.0;
    float log2_rmin = (float)(log(2.7) / log(2.0));
    float inv_log2_1pd = (float)(log(2.0) / log(1.0 + delta));

    // Exact floor(i / n_per_s) for i < 2^20: magic = ceil(2^40 / n_per_s)
    unsigned long long div_magic =
        ((1ULL << 40) + (unsigned long long)n_per_s - 1ULL) / (unsigned long long)n_per_s;

    // --- K1: index compute (triggers early for PDL overlap) ---
    int nchunks = (npts + 3) / 4;
    int k1_blocks = (nchunks + 255) / 256;
    k_indices<<<k1_blocks, 256>>>(
        (const float4*)lidars, r_bins, angle_bins,
        npts, num_r, num_a, div_magic,
        a0, inv_astep, log2_rmin, inv_log2_1pd);

    // --- K2: zero output, PDL-overlapped with K1 (independent memory) ---
    {
        int n4 = out_size / 4;
        int k2_blocks = 148 * 10;
        cudaLaunchConfig_t cfg = {};
        cfg.gridDim = dim3(k2_blocks, 1, 1);
        cfg.blockDim = dim3(256, 1, 1);
        cfg.dynamicSmemBytes = 0;
        cfg.stream = 0;
        cudaLaunchAttribute attr[1];
        attr[0].id = cudaLaunchAttributeProgrammaticStreamSerialization;
        attr[0].val.programmaticStreamSerializationAllowed = 1;
        cfg.attrs = attr;
        cfg.numAttrs = 1;
        float4* out4 = (float4*)out;
        cudaLaunchKernelEx(&cfg, k_zero, out4, n4);
    }

    // --- K3: scatter (normal launch: waits for BOTH K1 and K2) ---
    int k3_blocks = (npts + 255) / 256;
    k_scatter<<<k3_blocks, 256>>>(out, npts);
}